// round 15
// baseline (speedup 1.0000x reference)
#include <cuda_runtime.h>
#include <cuda_fp16.h>
#include <cuda_bf16.h>

// ROIAlign via fp16-NHWC pre-transpose (ROI Morton sort folded into transpose).
// Main kernel: ONE BLOCK PER ROI (224 thr), looping ph=0..6 in-block.
// Amortizes ROI prologue / x-weights 7x; ~1.35 scheduling waves.

#define B_    2
#define C_    256
#define H_    200
#define W_    272
#define HW_   (H_ * W_)
#define PH_   7
#define PW_   7
#define NBIN  (PH_ * PW_)
#define SCALE 0.25f
#define NMAX  1024
#define BINS  512              // 1 batch bit + 8 Morton bits

__device__ __half g_nhwc[(size_t)B_ * HW_ * C_];   // 55.7 MB scratch
__device__ int    g_perm[NMAX];

// ---------------- NCHW -> NHWC(fp16) transpose + folded ROI sort -----------
#define CT_  128
#define TP_  (CT_ + 4)

__global__ void transpose_kernel(const float* __restrict__ in,
                                 const float* __restrict__ rois, int N) {
    __shared__ float tile[32][TP_];            // [hw_local][c_local]
    __shared__ int hist[BINS], basearr[BINS], cur[BINS], csum[16], scanbuf[BINS];

    int b  = blockIdx.z;
    int gs = blockIdx.x * 32;                  // HW offset (HW_ = 32*1700 exact)
    int gc = blockIdx.y * CT_;                 // C offset  (C_  = 128*2  exact)
    int tx = threadIdx.x, ty = threadIdx.y;    // (32, 8)

    const float* src = in + ((size_t)b * C_ + gc) * HW_ + gs;
    #pragma unroll
    for (int j = 0; j < CT_; j += 8)
        tile[tx][j + ty] = __ldcs(src + (size_t)(j + ty) * HW_ + tx);
    __syncthreads();

    __half* dst = g_nhwc + (size_t)b * HW_ * C_ + gc;
    #pragma unroll
    for (int r = 0; r < 4; r++) {
        int row = r * 8 + ty;
        __half2 h0 = __floats2half2_rn(tile[row][4 * tx + 0], tile[row][4 * tx + 1]);
        __half2 h1 = __floats2half2_rn(tile[row][4 * tx + 2], tile[row][4 * tx + 3]);
        uint2 v;
        v.x = *reinterpret_cast<unsigned*>(&h0);
        v.y = *reinterpret_cast<unsigned*>(&h1);
        *reinterpret_cast<uint2*>(dst + (size_t)(gs + row) * C_ + 4 * tx) = v;
    }

    // -------- block (0,0,0): counting sort of ROIs by (batch|Morton8) ------
    if (blockIdx.x | blockIdx.y | blockIdx.z) return;
    int t    = ty * 32 + tx;       // 0..255
    int lane = t & 31, wid = t >> 5;

    hist[t] = 0;  cur[t] = 0;  hist[t + 256] = 0;  cur[t + 256] = 0;
    __syncthreads();

    unsigned keys[4];
    #pragma unroll
    for (int i = 0; i < 4; i++) {
        int idx = t + 256 * i;
        keys[i] = 0;
        if (idx < N) {
            const float* r = rois + (size_t)idx * 5;
            int   bb = (int)r[0];
            float cx = (r[1] + r[3]) * 0.5f * SCALE;
            float cy = (r[2] + r[4]) * 0.5f * SCALE;
            unsigned ux = (unsigned)fminf(fmaxf(cx * (16.0f / W_), 0.0f), 15.0f);
            unsigned uy = (unsigned)fminf(fmaxf(cy * (16.0f / H_), 0.0f), 15.0f);
            unsigned m = 0;
            #pragma unroll
            for (int k = 0; k < 4; k++)
                m |= (((ux >> k) & 1u) << (2 * k)) | (((uy >> k) & 1u) << (2 * k + 1));
            keys[i] = ((unsigned)bb << 8) | m;
            atomicAdd(&hist[keys[i]], 1);
        }
    }
    __syncthreads();

    #pragma unroll
    for (int j = 0; j < 2; j++) {
        int chunk = wid + 8 * j;
        int e = chunk * 32 + lane;
        int v = hist[e];
        #pragma unroll
        for (int o = 1; o < 32; o <<= 1) {
            int nb = __shfl_up_sync(0xffffffff, v, o);
            if (lane >= o) v += nb;
        }
        scanbuf[e] = v;
        if (lane == 31) csum[chunk] = v;
    }
    __syncthreads();
    if (t < 16) {
        int v = csum[t];
        #pragma unroll
        for (int o = 1; o < 16; o <<= 1) {
            int nb = __shfl_up_sync(0xffff, v, o);
            if (t >= o) v += nb;
        }
        csum[t] = v;
    }
    __syncthreads();
    #pragma unroll
    for (int j = 0; j < 2; j++) {
        int e = t + 256 * j;
        int chunk = e >> 5;
        basearr[e] = scanbuf[e] - hist[e] + (chunk ? csum[chunk - 1] : 0);
    }
    __syncthreads();

    #pragma unroll
    for (int i = 0; i < 4; i++) {
        int idx = t + 256 * i;
        if (idx < N) {
            int pos = basearr[keys[i]] + atomicAdd(&cur[keys[i]], 1);
            g_perm[pos] = idx;
        }
    }
}

// ---------------- main ROIAlign on fp16 NHWC, block-per-ROI -----------------
// 224 threads: c8 = tid&31 (8 channels, 16B loads -> one 512B warp request
// per corner), pw = tid>>5. Loop over ph inside the block; x-weights hoisted.
#define SROW (C_ + 8)

__global__ __launch_bounds__(224) void roialign_nhwc(const float* __restrict__ rois,
                                                     float* __restrict__ out,
                                                     int N) {
    int n   = g_perm[blockIdx.x];
    int tid = threadIdx.x;
    int c8  = tid & 31;
    int pw  = tid >> 5;          // 0..6

    __shared__ float s_out[PW_][SROW];

    const float* r = rois + (size_t)n * 5;
    int   b  = (int)__ldg(r + 0);
    float sw = __ldg(r + 1) * SCALE;
    float sh = __ldg(r + 2) * SCALE;
    float ew = __ldg(r + 3) * SCALE;
    float eh = __ldg(r + 4) * SCALE;

    float roi_w = fmaxf(ew - sw, 1.0f);
    float roi_h = fmaxf(eh - sh, 1.0f);
    float bin_w = roi_w * (1.0f / PW_);
    float bin_h = roi_h * (1.0f / PH_);

    // x side (independent of ph): per sample ix, corner columns + fp16 weights;
    // 0.25 * x-validity folded into the f32 y-stage weight.
    int     xlo[2], xhi[2];
    __half2 hx2[2], lx2[2];
    float   wvx[2];
    #pragma unroll
    for (int ix = 0; ix < 2; ix++) {
        float x  = sw + ((float)pw + ((float)ix + 0.5f) * 0.5f) * bin_w;
        wvx[ix]  = ((x > -1.0f) && (x < (float)W_)) ? 0.25f : 0.0f;
        float xc = fminf(fmaxf(x, 0.0f), (float)(W_ - 1));
        int   xl = (int)floorf(xc);
        xlo[ix]  = xl;
        xhi[ix]  = min(xl + 1, W_ - 1);
        float lx = xc - (float)xl;
        hx2[ix]  = __float2half2_rn(1.0f - lx);
        lx2[ix]  = __float2half2_rn(lx);
    }

    const __half* pbase   = g_nhwc + c8 * 8;
    float*        obase_n = out + (size_t)n * C_ * NBIN;

    for (int ph = 0; ph < PH_; ph++) {
        // y side for this ph: 4 corner rows, validity folded into weight
        int   rowoff[4];
        float wy[4];
        #pragma unroll
        for (int iy = 0; iy < 2; iy++) {
            float y  = sh + ((float)ph + ((float)iy + 0.5f) * 0.5f) * bin_h;
            float vy = ((y > -1.0f) && (y < (float)H_)) ? 1.0f : 0.0f;
            float yc = fminf(fmaxf(y, 0.0f), (float)(H_ - 1));
            int   yl = (int)floorf(yc);
            int   yh = min(yl + 1, H_ - 1);
            float ly = yc - (float)yl;
            rowoff[iy * 2 + 0] = (b * H_ + yl) * W_;
            rowoff[iy * 2 + 1] = (b * H_ + yh) * W_;
            wy[iy * 2 + 0] = (1.0f - ly) * vy;
            wy[iy * 2 + 1] = ly * vy;
        }

        float acc[8] = {0.f, 0.f, 0.f, 0.f, 0.f, 0.f, 0.f, 0.f};
        #pragma unroll
        for (int yc = 0; yc < 4; yc++) {
            const size_t rbase = (size_t)rowoff[yc] * C_;
            // issue all 4 loads for this y-corner before any math (MLP=4)
            uint4 rl0 = __ldg(reinterpret_cast<const uint4*>(pbase + rbase + (size_t)xlo[0] * C_));
            uint4 rh0 = __ldg(reinterpret_cast<const uint4*>(pbase + rbase + (size_t)xhi[0] * C_));
            uint4 rl1 = __ldg(reinterpret_cast<const uint4*>(pbase + rbase + (size_t)xlo[1] * C_));
            uint4 rh1 = __ldg(reinterpret_cast<const uint4*>(pbase + rbase + (size_t)xhi[1] * C_));

            #pragma unroll
            for (int ix = 0; ix < 2; ix++) {
                uint4& rl = ix ? rl1 : rl0;
                uint4& rh = ix ? rh1 : rh0;
                // fp16 x-interp: a = hx*v_xl + lx*v_xh  (4 half2 lanes = 8 ch)
                __half2 a0 = __hfma2(lx2[ix], *reinterpret_cast<__half2*>(&rh.x),
                             __hmul2(hx2[ix], *reinterpret_cast<__half2*>(&rl.x)));
                __half2 a1 = __hfma2(lx2[ix], *reinterpret_cast<__half2*>(&rh.y),
                             __hmul2(hx2[ix], *reinterpret_cast<__half2*>(&rl.y)));
                __half2 a2 = __hfma2(lx2[ix], *reinterpret_cast<__half2*>(&rh.z),
                             __hmul2(hx2[ix], *reinterpret_cast<__half2*>(&rl.z)));
                __half2 a3 = __hfma2(lx2[ix], *reinterpret_cast<__half2*>(&rh.w),
                             __hmul2(hx2[ix], *reinterpret_cast<__half2*>(&rl.w)));

                float w = wy[yc] * wvx[ix];
                float2 f0 = __half22float2(a0);
                float2 f1 = __half22float2(a1);
                float2 f2 = __half22float2(a2);
                float2 f3 = __half22float2(a3);
                acc[0] = fmaf(w, f0.x, acc[0]);  acc[1] = fmaf(w, f0.y, acc[1]);
                acc[2] = fmaf(w, f1.x, acc[2]);  acc[3] = fmaf(w, f1.y, acc[3]);
                acc[4] = fmaf(w, f2.x, acc[4]);  acc[5] = fmaf(w, f2.y, acc[5]);
                acc[6] = fmaf(w, f3.x, acc[6]);  acc[7] = fmaf(w, f3.y, acc[7]);
            }
        }

        float4* srow = reinterpret_cast<float4*>(&s_out[pw][0]) + c8 * 2;
        srow[0] = make_float4(acc[0], acc[1], acc[2], acc[3]);
        srow[1] = make_float4(acc[4], acc[5], acc[6], acc[7]);
        __syncthreads();

        float* obase = obase_n + ph * PW_;
        #pragma unroll 8
        for (int i = tid; i < C_ * PW_; i += 224) {
            int c  = i / PW_;
            int p2 = i - c * PW_;
            __stcs(obase + c * NBIN + p2, s_out[p2][c]);
        }
        __syncthreads();
    }
}

extern "C" void kernel_launch(void* const* d_in, const int* in_sizes, int n_in,
                              void* d_out, int out_size) {
    const float* feat = (const float*)d_in[0];
    const float* rois = (const float*)d_in[1];
    float*       out  = (float*)d_out;

    int N = in_sizes[1] / 5;

    dim3 tg(HW_ / 32, C_ / CT_, B_);
    transpose_kernel<<<tg, dim3(32, 8)>>>(feat, rois, N);

    roialign_nhwc<<<N, 224>>>(rois, out, N);
}

// round 17
// speedup vs baseline: 1.2557x; 1.2557x over previous
#include <cuda_runtime.h>
#include <cuda_fp16.h>
#include <cuda_bf16.h>

// ROIAlign via fp16-NHWC pre-transpose (ROI Morton sort folded into transpose).
// R7 main kernel (best measured: 42.1us) + Morton 32x32 counting sort.

#define B_    2
#define C_    256
#define H_    200
#define W_    272
#define HW_   (H_ * W_)
#define PH_   7
#define PW_   7
#define NBIN  (PH_ * PW_)
#define SCALE 0.25f
#define NMAX  1024
#define BINS  2048             // 1 batch bit + 10 Morton bits (32x32)

__device__ __half g_nhwc[(size_t)B_ * HW_ * C_];   // 55.7 MB scratch
__device__ int    g_perm[NMAX];

// ---------------- NCHW -> NHWC(fp16) transpose + folded ROI sort -----------
#define CT_  128
#define TP_  (CT_ + 4)

__global__ void transpose_kernel(const float* __restrict__ in,
                                 const float* __restrict__ rois, int N) {
    __shared__ float tile[32][TP_];            // [hw_local][c_local]
    __shared__ int hist[BINS], basearr[BINS], cur[BINS], wsum[8];

    int b  = blockIdx.z;
    int gs = blockIdx.x * 32;                  // HW offset (HW_ = 32*1700 exact)
    int gc = blockIdx.y * CT_;                 // C offset  (C_  = 128*2  exact)
    int tx = threadIdx.x, ty = threadIdx.y;    // (32, 8)

    const float* src = in + ((size_t)b * C_ + gc) * HW_ + gs;
    #pragma unroll
    for (int j = 0; j < CT_; j += 8)
        tile[tx][j + ty] = __ldcs(src + (size_t)(j + ty) * HW_ + tx);
    __syncthreads();

    __half* dst = g_nhwc + (size_t)b * HW_ * C_ + gc;
    #pragma unroll
    for (int r = 0; r < 4; r++) {
        int row = r * 8 + ty;
        __half2 h0 = __floats2half2_rn(tile[row][4 * tx + 0], tile[row][4 * tx + 1]);
        __half2 h1 = __floats2half2_rn(tile[row][4 * tx + 2], tile[row][4 * tx + 3]);
        uint2 v;
        v.x = *reinterpret_cast<unsigned*>(&h0);
        v.y = *reinterpret_cast<unsigned*>(&h1);
        *reinterpret_cast<uint2*>(dst + (size_t)(gs + row) * C_ + 4 * tx) = v;
    }

    // -------- block (0,0,0): counting sort of ROIs by (batch|Morton10) -----
    if (blockIdx.x | blockIdx.y | blockIdx.z) return;
    int t    = ty * 32 + tx;       // 0..255
    int lane = t & 31, wid = t >> 5;

    #pragma unroll
    for (int j = 0; j < 8; j++) { hist[t + 256 * j] = 0; cur[t + 256 * j] = 0; }
    __syncthreads();

    unsigned keys[4];
    #pragma unroll
    for (int i = 0; i < 4; i++) {
        int idx = t + 256 * i;
        keys[i] = 0;
        if (idx < N) {
            const float* r = rois + (size_t)idx * 5;
            int   bb = (int)r[0];
            float cx = (r[1] + r[3]) * 0.5f * SCALE;
            float cy = (r[2] + r[4]) * 0.5f * SCALE;
            unsigned ux = (unsigned)fminf(fmaxf(cx * (32.0f / W_), 0.0f), 31.0f);
            unsigned uy = (unsigned)fminf(fmaxf(cy * (32.0f / H_), 0.0f), 31.0f);
            unsigned m = 0;
            #pragma unroll
            for (int k = 0; k < 5; k++)
                m |= (((ux >> k) & 1u) << (2 * k)) | (((uy >> k) & 1u) << (2 * k + 1));
            keys[i] = ((unsigned)bb << 10) | m;
            atomicAdd(&hist[keys[i]], 1);
        }
    }
    __syncthreads();

    // exclusive scan of hist[2048]: 8 bins/thread + warp scan + 8-way top scan
    int loc[8], s = 0;
    #pragma unroll
    for (int k = 0; k < 8; k++) { loc[k] = s; s += hist[t * 8 + k]; }
    int incl = s;
    #pragma unroll
    for (int o = 1; o < 32; o <<= 1) {
        int nb = __shfl_up_sync(0xffffffff, incl, o);
        if (lane >= o) incl += nb;
    }
    int excl = incl - s;
    if (lane == 31) wsum[wid] = incl;
    __syncthreads();
    if (t < 8) {
        int v = wsum[t];
        #pragma unroll
        for (int o = 1; o < 8; o <<= 1) {
            int nb = __shfl_up_sync(0xff, v, o);
            if (t >= o) v += nb;
        }
        wsum[t] = v;               // inclusive warp sums
    }
    __syncthreads();
    int wbase = (wid ? wsum[wid - 1] : 0) + excl;
    #pragma unroll
    for (int k = 0; k < 8; k++) basearr[t * 8 + k] = wbase + loc[k];
    __syncthreads();

    #pragma unroll
    for (int i = 0; i < 4; i++) {
        int idx = t + 256 * i;
        if (idx < N) {
            int pos = basearr[keys[i]] + atomicAdd(&cur[keys[i]], 1);
            g_perm[pos] = idx;
        }
    }
}

// ---------------- main ROIAlign on fp16 NHWC (R7 form, 42.1us) -------------
// Block = one (ph, sorted-roi). 224 threads: c8 = tid&31 (8 channels, 16B
// loads -> one 512B warp request per corner), pw = tid>>5.
#define SROW (C_ + 8)

__global__ __launch_bounds__(224) void roialign_nhwc(const float* __restrict__ rois,
                                                     float* __restrict__ out,
                                                     int N) {
    int n   = g_perm[blockIdx.y];
    int ph  = blockIdx.x;
    int tid = threadIdx.x;
    int c8  = tid & 31;
    int pw  = tid >> 5;          // 0..6

    __shared__ float s_out[PW_][SROW];

    const float* r = rois + (size_t)n * 5;
    int   b  = (int)__ldg(r + 0);
    float sw = __ldg(r + 1) * SCALE;
    float sh = __ldg(r + 2) * SCALE;
    float ew = __ldg(r + 3) * SCALE;
    float eh = __ldg(r + 4) * SCALE;

    float roi_w = fmaxf(ew - sw, 1.0f);
    float roi_h = fmaxf(eh - sh, 1.0f);
    float bin_w = roi_w * (1.0f / PW_);
    float bin_h = roi_h * (1.0f / PH_);

    int   offs[16];
    float wts[16];

    #pragma unroll
    for (int iy = 0; iy < 2; iy++) {
        float y  = sh + ((float)ph + ((float)iy + 0.5f) * 0.5f) * bin_h;
        bool  vy = (y > -1.0f) && (y < (float)H_);
        float yc = fminf(fmaxf(y, 0.0f), (float)(H_ - 1));
        int   yl = (int)floorf(yc);
        int   yh = min(yl + 1, H_ - 1);
        float ly = yc - (float)yl;
        float hy = 1.0f - ly;
        #pragma unroll
        for (int ix = 0; ix < 2; ix++) {
            float x  = sw + ((float)pw + ((float)ix + 0.5f) * 0.5f) * bin_w;
            bool  vx = (x > -1.0f) && (x < (float)W_);
            float xc = fminf(fmaxf(x, 0.0f), (float)(W_ - 1));
            int   xl = (int)floorf(xc);
            int   xh = min(xl + 1, W_ - 1);
            float lx = xc - (float)xl;
            float hx = 1.0f - lx;

            float v = (vy && vx) ? 0.25f : 0.0f;   // 1/(sr*sr), masked
            int rowl = (b * H_ + yl) * W_;
            int rowh = (b * H_ + yh) * W_;
            int k = (iy * 2 + ix) * 4;
            offs[k + 0] = (rowl + xl) * C_;  wts[k + 0] = hy * hx * v;
            offs[k + 1] = (rowl + xh) * C_;  wts[k + 1] = hy * lx * v;
            offs[k + 2] = (rowh + xl) * C_;  wts[k + 2] = ly * hx * v;
            offs[k + 3] = (rowh + xh) * C_;  wts[k + 3] = ly * lx * v;
        }
    }

    float acc[8] = {0.f, 0.f, 0.f, 0.f, 0.f, 0.f, 0.f, 0.f};
    #pragma unroll
    for (int k = 0; k < 16; k++) {
        const uint4* p = reinterpret_cast<const uint4*>(g_nhwc + offs[k]) + c8;
        uint4 raw = __ldg(p);
        float w = wts[k];
        __half2 h0 = *reinterpret_cast<__half2*>(&raw.x);
        __half2 h1 = *reinterpret_cast<__half2*>(&raw.y);
        __half2 h2 = *reinterpret_cast<__half2*>(&raw.z);
        __half2 h3 = *reinterpret_cast<__half2*>(&raw.w);
        float2 f0 = __half22float2(h0);
        float2 f1 = __half22float2(h1);
        float2 f2 = __half22float2(h2);
        float2 f3 = __half22float2(h3);
        acc[0] = fmaf(w, f0.x, acc[0]);  acc[1] = fmaf(w, f0.y, acc[1]);
        acc[2] = fmaf(w, f1.x, acc[2]);  acc[3] = fmaf(w, f1.y, acc[3]);
        acc[4] = fmaf(w, f2.x, acc[4]);  acc[5] = fmaf(w, f2.y, acc[5]);
        acc[6] = fmaf(w, f3.x, acc[6]);  acc[7] = fmaf(w, f3.y, acc[7]);
    }

    float4* srow = reinterpret_cast<float4*>(&s_out[pw][0]) + c8 * 2;
    srow[0] = make_float4(acc[0], acc[1], acc[2], acc[3]);
    srow[1] = make_float4(acc[4], acc[5], acc[6], acc[7]);
    __syncthreads();

    float* obase = out + (size_t)n * C_ * NBIN + ph * PW_;
    #pragma unroll 8
    for (int i = tid; i < C_ * PW_; i += 224) {
        int c  = i / PW_;
        int p2 = i - c * PW_;
        __stcs(obase + c * NBIN + p2, s_out[p2][c]);
    }
}

extern "C" void kernel_launch(void* const* d_in, const int* in_sizes, int n_in,
                              void* d_out, int out_size) {
    const float* feat = (const float*)d_in[0];
    const float* rois = (const float*)d_in[1];
    float*       out  = (float*)d_out;

    int N = in_sizes[1] / 5;

    dim3 tg(HW_ / 32, C_ / CT_, B_);
    transpose_kernel<<<tg, dim3(32, 8)>>>(feat, rois, N);

    dim3 mg(PH_, N);
    roialign_nhwc<<<mg, 224>>>(rois, out, N);
}